// round 1
// baseline (speedup 1.0000x reference)
#include <cuda_runtime.h>

#define N_PTS 32768
#define DIM   512
#define KC    2048
#define DECAYF 0.99f

// ---- output layout (float32, concat order: quantized, indices, new_centroids, new_size, new_w) ----
#define OFF_Q   ((size_t)0)
#define OFF_IDX ((size_t)N_PTS * DIM)
#define OFF_NC  (OFF_IDX + N_PTS)
#define OFF_NS  (OFF_NC + (size_t)KC * DIM)
#define OFF_NW  (OFF_NS + KC)

// ---- scratch (device globals; no allocation allowed) ----
__device__ float g_cnorm2[KC];
__device__ float g_invn[N_PTS];
__device__ float g_dw[KC * DIM];
__device__ float g_counts[KC];
__device__ int   g_idx[N_PTS];
__device__ float g_ns[KC];

// ================= kernel 0: zero scratch accumulators (must rerun every graph replay) ============
__global__ void k_zero() {
    int i = blockIdx.x * blockDim.x + threadIdx.x;           // 262144 threads
    ((float4*)g_dw)[i] = make_float4(0.f, 0.f, 0.f, 0.f);
    if (i < KC) g_counts[i] = 0.f;
}

// ================= kernel 1: centroid norms^2 + X inverse norms ===================================
__global__ void k_norms(const float* __restrict__ X, const float* __restrict__ C) {
    int warp = (blockIdx.x * blockDim.x + threadIdx.x) >> 5;
    int lane = threadIdx.x & 31;
    if (warp < KC) {
        const float4* r = (const float4*)(C + (size_t)warp * DIM);
        float s = 0.f;
        #pragma unroll
        for (int i = lane; i < DIM / 4; i += 32) {
            float4 v = r[i];
            s += v.x * v.x + v.y * v.y + v.z * v.z + v.w * v.w;
        }
        #pragma unroll
        for (int o = 16; o; o >>= 1) s += __shfl_xor_sync(0xFFFFFFFFu, s, o);
        if (lane == 0) g_cnorm2[warp] = s;
    } else if (warp < KC + N_PTS) {
        int row = warp - KC;
        const float4* r = (const float4*)(X + (size_t)row * DIM);
        float s = 0.f;
        #pragma unroll
        for (int i = lane; i < DIM / 4; i += 32) {
            float4 v = r[i];
            s += v.x * v.x + v.y * v.y + v.z * v.z + v.w * v.w;
        }
        #pragma unroll
        for (int o = 16; o; o >>= 1) s += __shfl_xor_sync(0xFFFFFFFFu, s, o);
        if (lane == 0) {
            float nrm = sqrtf(s);
            g_invn[row] = 1.0f / fmaxf(nrm, 1e-12f);
        }
    }
}

// ================= kernel 2: fused GEMM + argmin ==================================================
// block = 128 rows of X; loops over 16 column tiles of 128 centroids; K=512 in chunks of 32.
// 256 threads, each computes an 8x8 accumulator patch.
union SmemU {
    struct { float A[32][132]; float B[32][132]; } t;     // 33792 B
    unsigned long long red[128][16];                      // 16384 B
};

__global__ __launch_bounds__(256) void k_assign(const float* __restrict__ X,
                                                const float* __restrict__ C,
                                                float* __restrict__ out) {
    __shared__ SmemU sm;
    const int tid = threadIdx.x;
    const int tx = tid & 15;          // column group (8 cols)
    const int ty = tid >> 4;          // row group (8 rows)
    const int r0 = blockIdx.x * 128;

    float inv[8];
    unsigned long long best[8];
    #pragma unroll
    for (int i = 0; i < 8; i++) {
        inv[i] = g_invn[r0 + ty * 8 + i];
        best[i] = ~0ull;
    }

    for (int ct = 0; ct < KC / 128; ++ct) {
        float acc[8][8];
        #pragma unroll
        for (int i = 0; i < 8; i++)
            #pragma unroll
            for (int j = 0; j < 8; j++) acc[i][j] = 0.f;

        for (int kb = 0; kb < DIM / 32; ++kb) {
            // cooperative loads: 1024 float4 per tile, 4 per thread
            #pragma unroll
            for (int t = 0; t < 4; t++) {
                int idx = tid + t * 256;
                int row = idx >> 3;
                int k4  = idx & 7;
                float4 va = *(const float4*)(X + (size_t)(r0 + row) * DIM + kb * 32 + k4 * 4);
                sm.t.A[k4 * 4 + 0][row] = va.x;
                sm.t.A[k4 * 4 + 1][row] = va.y;
                sm.t.A[k4 * 4 + 2][row] = va.z;
                sm.t.A[k4 * 4 + 3][row] = va.w;
                float4 vb = *(const float4*)(C + (size_t)(ct * 128 + row) * DIM + kb * 32 + k4 * 4);
                sm.t.B[k4 * 4 + 0][row] = vb.x;
                sm.t.B[k4 * 4 + 1][row] = vb.y;
                sm.t.B[k4 * 4 + 2][row] = vb.z;
                sm.t.B[k4 * 4 + 3][row] = vb.w;
            }
            __syncthreads();
            #pragma unroll
            for (int k = 0; k < 32; k++) {
                float4 a0 = *(const float4*)&sm.t.A[k][ty * 8];
                float4 a1 = *(const float4*)&sm.t.A[k][ty * 8 + 4];
                float4 b0 = *(const float4*)&sm.t.B[k][tx * 8];
                float4 b1 = *(const float4*)&sm.t.B[k][tx * 8 + 4];
                float a[8] = {a0.x, a0.y, a0.z, a0.w, a1.x, a1.y, a1.z, a1.w};
                float b[8] = {b0.x, b0.y, b0.z, b0.w, b1.x, b1.y, b1.z, b1.w};
                #pragma unroll
                for (int i = 0; i < 8; i++)
                    #pragma unroll
                    for (int j = 0; j < 8; j++) acc[i][j] = fmaf(a[i], b[j], acc[i][j]);
            }
            __syncthreads();
        }

        // epilogue: dist = ||c||^2 - 2*invn*dot (the +||xn||^2 term is row-constant, argmin-invariant)
        #pragma unroll
        for (int j = 0; j < 8; j++) {
            int col = ct * 128 + tx * 8 + j;
            float cn = __ldg(&g_cnorm2[col]);
            #pragma unroll
            for (int i = 0; i < 8; i++) {
                float d = fmaf(-2.0f * inv[i], acc[i][j], cn);
                unsigned int u = __float_as_uint(d);
                u = (u & 0x80000000u) ? ~u : (u | 0x80000000u);   // order-preserving map
                unsigned long long key = ((unsigned long long)u << 32) | (unsigned int)col;
                if (key < best[i]) best[i] = key;
            }
        }
    }

    // cross-thread argmin reduction (columns spread over tx)
    #pragma unroll
    for (int i = 0; i < 8; i++) sm.red[ty * 8 + i][tx] = best[i];
    __syncthreads();
    if (tid < 128) {
        unsigned long long m = sm.red[tid][0];
        #pragma unroll
        for (int t = 1; t < 16; t++) {
            unsigned long long v = sm.red[tid][t];
            m = v < m ? v : m;
        }
        int k = (int)(unsigned int)(m & 0xffffffffull);
        int row = r0 + tid;
        g_idx[row] = k;
        out[OFF_IDX + row] = (float)k;
        atomicAdd(&g_counts[k], 1.0f);
    }
}

// ================= kernel 3: quantized gather + dw scatter ========================================
__global__ void k_scatter(const float* __restrict__ X, const float* __restrict__ C,
                          float* __restrict__ out) {
    int row  = blockIdx.x * 8 + (threadIdx.x >> 5);
    int lane = threadIdx.x & 31;
    int k = g_idx[row];
    const float4* c4 = (const float4*)(C + (size_t)k * DIM);
    const float4* x4 = (const float4*)(X + (size_t)row * DIM);
    float4* q4 = (float4*)(out + OFF_Q + (size_t)row * DIM);
    float* dwr = g_dw + (size_t)k * DIM;
    #pragma unroll
    for (int i = lane; i < DIM / 4; i += 32) {
        q4[i] = c4[i];                       // quantized = centroids[idx]
        float4 v = x4[i];
        atomicAdd(dwr + i * 4 + 0, v.x);     // dw = onehot.T @ X (raw sum; scaled at finalize)
        atomicAdd(dwr + i * 4 + 1, v.y);
        atomicAdd(dwr + i * 4 + 2, v.z);
        atomicAdd(dwr + i * 4 + 3, v.w);
    }
}

// ================= kernel 4: EMA cluster size (single block) ======================================
__global__ void k_size(const float* __restrict__ ema_size, float* __restrict__ out) {
    __shared__ float s0[KC];
    __shared__ float part[1024];
    int tid = threadIdx.x;
    const float om = 1.0f - DECAYF;
    float local = 0.f;
    for (int k = tid; k < KC; k += 1024) {
        float v = ema_size[k] * DECAYF + om * g_counts[k];
        s0[k] = v;
        local += v;
    }
    part[tid] = local;
    __syncthreads();
    for (int o = 512; o > 0; o >>= 1) {
        if (tid < o) part[tid] += part[tid + o];
        __syncthreads();
    }
    float n = part[0];
    float denom = n + (float)KC * 1e-5f;
    for (int k = tid; k < KC; k += 1024) {
        float ns = (s0[k] + 1e-5f) / denom * n;
        out[OFF_NS + k] = ns;
        g_ns[k] = ns;
    }
}

// ================= kernel 5: new_w + new_centroids ================================================
__global__ void k_final(const float* __restrict__ ema_w, float* __restrict__ out) {
    int i = blockIdx.x * blockDim.x + threadIdx.x;     // float4 index, 262144 total
    int k = i >> 7;                                    // 128 float4 per row
    const float om = 1.0f - DECAYF;
    float4 w = ((const float4*)ema_w)[i];
    float4 d = ((const float4*)g_dw)[i];
    float4 nw;
    nw.x = w.x * DECAYF + om * d.x;
    nw.y = w.y * DECAYF + om * d.y;
    nw.z = w.z * DECAYF + om * d.z;
    nw.w = w.w * DECAYF + om * d.w;
    ((float4*)(out + OFF_NW))[i] = nw;
    float ns = __ldg(&g_ns[k]);
    float4 nc;
    nc.x = nw.x / ns;
    nc.y = nw.y / ns;
    nc.z = nw.z / ns;
    nc.w = nw.w / ns;
    ((float4*)(out + OFF_NC))[i] = nc;
}

// ================= launch ========================================================================
extern "C" void kernel_launch(void* const* d_in, const int* in_sizes, int n_in,
                              void* d_out, int out_size) {
    const float* X        = (const float*)d_in[0];
    const float* C        = (const float*)d_in[1];
    const float* ema_size = (const float*)d_in[2];
    const float* ema_w    = (const float*)d_in[3];
    float* out = (float*)d_out;

    k_zero   <<<(KC * DIM / 4) / 256, 256>>>();
    k_norms  <<<(KC + N_PTS) / 8, 256>>>(X, C);
    k_assign <<<N_PTS / 128, 256>>>(X, C, out);
    k_scatter<<<N_PTS / 8, 256>>>(X, C, out);
    k_size   <<<1, 1024>>>(ema_size, out);
    k_final  <<<(KC * DIM / 4) / 256, 256>>>(ema_w, out);
}

// round 5
// speedup vs baseline: 2.5281x; 2.5281x over previous
#include <cuda_runtime.h>
#include <cuda_bf16.h>
#include <cstdint>

#define N_PTS 32768
#define DIM   512
#define KC    2048
#define DECAYF 0.99f
#define MARGIN 0.25f

// ---- output layout (float32, concat: quantized, indices, new_centroids, new_size, new_w) ----
#define OFF_Q   ((size_t)0)
#define OFF_IDX ((size_t)N_PTS * DIM)
#define OFF_NC  (OFF_IDX + N_PTS)
#define OFF_NS  (OFF_NC + (size_t)KC * DIM)
#define OFF_NW  (OFF_NS + KC)

// ---- scratch (device globals) ----
__device__ float g_cnorm2[KC];
__device__ float g_invn[N_PTS];
__device__ float g_dw[KC * DIM];
__device__ float g_counts[KC];
__device__ int   g_idx[N_PTS];
__device__ float g_ns[KC];
__device__ __nv_bfloat16 g_xn[(size_t)N_PTS * DIM];   // normalized X, bf16
__device__ __nv_bfloat16 g_cb[(size_t)KC * DIM];      // centroids, bf16

// ---- smem layout for k_assign_mma (bytes) ----
// A: 8 chunks of [128 rows][72 halves] = 8 * 18432 = 147456
// B: 2 buffers  of [128 rows][72 halves] = 36864   @ 147456
// cn: 2048 f32 = 8192                              @ 184320
// red: [128][8] u64 = 8192                         @ 192512
#define CHUNK_B   18432
#define LDH       72
#define AOFF      0
#define BOFF      147456
#define CNOFF     184320
#define REDOFF    192512
#define SMEM_DYN  200704

__device__ __forceinline__ unsigned long long packkey(float d, int col) {
    unsigned int u = __float_as_uint(d);
    u = (u & 0x80000000u) ? ~u : (u | 0x80000000u);
    return ((unsigned long long)u << 32) | (unsigned int)col;
}
__device__ __forceinline__ float unpackd(unsigned long long k) {
    unsigned int u = (unsigned int)(k >> 32);
    u = (u & 0x80000000u) ? (u ^ 0x80000000u) : ~u;
    return __uint_as_float(u);
}
__device__ __forceinline__ void ins2(unsigned long long v,
                                     unsigned long long& r0, unsigned long long& r1) {
    if (v < r0) { r1 = r0; r0 = v; } else if (v < r1) { r1 = v; }
}

// ================= kernel 0: zero scratch ============
__global__ void k_zero() {
    int i = blockIdx.x * blockDim.x + threadIdx.x;
    ((float4*)g_dw)[i] = make_float4(0.f, 0.f, 0.f, 0.f);
    if (i < KC) g_counts[i] = 0.f;
}

// ================= kernel 1: norms + bf16 conversion ==============
__global__ void k_norms(const float* __restrict__ X, const float* __restrict__ C) {
    int warp = (blockIdx.x * blockDim.x + threadIdx.x) >> 5;
    int lane = threadIdx.x & 31;
    if (warp < KC) {
        const float4* r = (const float4*)(C + (size_t)warp * DIM);
        float s = 0.f;
        float4 v[4];
        #pragma unroll
        for (int t = 0; t < 4; t++) {
            v[t] = r[lane + t * 32];
            s += v[t].x * v[t].x + v[t].y * v[t].y + v[t].z * v[t].z + v[t].w * v[t].w;
        }
        #pragma unroll
        for (int o = 16; o; o >>= 1) s += __shfl_xor_sync(0xFFFFFFFFu, s, o);
        if (lane == 0) g_cnorm2[warp] = s;
        __nv_bfloat162* ob = (__nv_bfloat162*)(g_cb + (size_t)warp * DIM);
        #pragma unroll
        for (int t = 0; t < 4; t++) {
            int i = lane + t * 32;
            ob[i * 2 + 0] = __floats2bfloat162_rn(v[t].x, v[t].y);
            ob[i * 2 + 1] = __floats2bfloat162_rn(v[t].z, v[t].w);
        }
    } else if (warp < KC + N_PTS) {
        int row = warp - KC;
        const float4* r = (const float4*)(X + (size_t)row * DIM);
        float s = 0.f;
        float4 v[4];
        #pragma unroll
        for (int t = 0; t < 4; t++) {
            v[t] = r[lane + t * 32];
            s += v[t].x * v[t].x + v[t].y * v[t].y + v[t].z * v[t].z + v[t].w * v[t].w;
        }
        #pragma unroll
        for (int o = 16; o; o >>= 1) s += __shfl_xor_sync(0xFFFFFFFFu, s, o);
        float in = 1.0f / fmaxf(sqrtf(s), 1e-12f);
        if (lane == 0) g_invn[row] = in;
        __nv_bfloat162* ob = (__nv_bfloat162*)(g_xn + (size_t)row * DIM);
        #pragma unroll
        for (int t = 0; t < 4; t++) {
            int i = lane + t * 32;
            ob[i * 2 + 0] = __floats2bfloat162_rn(v[t].x * in, v[t].y * in);
            ob[i * 2 + 1] = __floats2bfloat162_rn(v[t].z * in, v[t].w * in);
        }
    }
}

// ================= kernel 2: HMMA GEMM + argmin + exact refine =================
__global__ __launch_bounds__(256, 1) void k_assign_mma(const float* __restrict__ X,
                                                       const float* __restrict__ C,
                                                       float* __restrict__ out) {
    extern __shared__ char dsm[];
    float* s_cn = (float*)(dsm + CNOFF);
    unsigned long long* red = (unsigned long long*)(dsm + REDOFF);

    const int tid = threadIdx.x;
    const int lane = tid & 31;
    const int wid = tid >> 5;
    const int wm = wid >> 2;          // warp row strip (0..1), 64 rows each
    const int wn = wid & 3;           // warp col strip (0..3), 32 cols each
    const int g = lane >> 2;          // group id (0..7)
    const int tq = lane & 3;          // thread in group (0..3)
    const int r0 = blockIdx.x * 128;

    // ---- preload centroid norms ----
    for (int i = tid; i < KC; i += 256) s_cn[i] = g_cnorm2[i];

    // ---- load full A (128 rows x 512 bf16) into 8 padded chunks ----
    {
        const char* xbase = (const char*)g_xn;
        #pragma unroll
        for (int t = 0; t < 32; t++) {
            int idx = tid + t * 256;            // 8192 float4
            int chunk = idx >> 10;
            int r = (idx >> 3) & 127;
            int c4 = idx & 7;
            float4 v = *(const float4*)(xbase + ((size_t)(r0 + r) * DIM + chunk * 64 + c4 * 8) * 2);
            *(float4*)(dsm + AOFF + chunk * CHUNK_B + r * (LDH * 2) + c4 * 16) = v;
        }
    }

    // ---- load first B chunk (ct=0, kb=0) into buffer 0 ----
    {
        #pragma unroll
        for (int t = 0; t < 4; t++) {
            int idx = tid + t * 256;
            int r = idx >> 3;
            int c4 = idx & 7;
            float4 v = *(const float4*)((const char*)g_cb + ((size_t)r * DIM + c4 * 8) * 2);
            *(float4*)(dsm + BOFF + r * (LDH * 2) + c4 * 16) = v;
        }
    }
    __syncthreads();

    // per-thread running top-2 for 2 tracked rows (rows with mt == tq, rs = 0/1)
    unsigned long long rb0[2] = {~0ull, ~0ull};
    unsigned long long rb1[2] = {~0ull, ~0ull};

    for (int ct = 0; ct < 16; ++ct) {
        float acc[4][4][4];
        #pragma unroll
        for (int mt = 0; mt < 4; mt++)
            #pragma unroll
            for (int nt = 0; nt < 4; nt++)
                #pragma unroll
                for (int c = 0; c < 4; c++) acc[mt][nt][c] = 0.f;

        for (int kb = 0; kb < 8; ++kb) {
            // ---- prefetch next B chunk into registers ----
            int nct = ct, nkb = kb + 1;
            if (nkb == 8) { nkb = 0; nct = ct + 1; }
            if (nct == 16) { nct = 15; nkb = 7; }          // harmless tail reload
            float4 pre[4];
            #pragma unroll
            for (int t = 0; t < 4; t++) {
                int idx = tid + t * 256;
                int r = idx >> 3;
                int c4 = idx & 7;
                pre[t] = *(const float4*)((const char*)g_cb +
                          ((size_t)(nct * 128 + r) * DIM + nkb * 64 + c4 * 8) * 2);
            }

            // ---- MMA on current chunk ----
            const char* Ab = dsm + AOFF + kb * CHUNK_B;
            const char* Bb = dsm + BOFF + (kb & 1) * CHUNK_B;
            #pragma unroll
            for (int ks = 0; ks < 4; ks++) {
                const int k0 = ks * 16;
                uint32_t a[4][4];
                #pragma unroll
                for (int mt = 0; mt < 4; mt++) {
                    const char* ab = Ab + (wm * 64 + mt * 16 + g) * (LDH * 2) + (k0 + 2 * tq) * 2;
                    a[mt][0] = *(const uint32_t*)(ab);
                    a[mt][1] = *(const uint32_t*)(ab + 8 * (LDH * 2));
                    a[mt][2] = *(const uint32_t*)(ab + 16);
                    a[mt][3] = *(const uint32_t*)(ab + 8 * (LDH * 2) + 16);
                }
                #pragma unroll
                for (int nt = 0; nt < 4; nt++) {
                    const char* bb = Bb + (wn * 32 + nt * 8 + g) * (LDH * 2) + (k0 + 2 * tq) * 2;
                    uint32_t b0 = *(const uint32_t*)(bb);
                    uint32_t b1 = *(const uint32_t*)(bb + 16);
                    #pragma unroll
                    for (int mt = 0; mt < 4; mt++) {
                        asm volatile(
                            "mma.sync.aligned.m16n8k16.row.col.f32.bf16.bf16.f32 "
                            "{%0,%1,%2,%3}, {%4,%5,%6,%7}, {%8,%9}, {%0,%1,%2,%3};"
                            : "+f"(acc[mt][nt][0]), "+f"(acc[mt][nt][1]),
                              "+f"(acc[mt][nt][2]), "+f"(acc[mt][nt][3])
                            : "r"(a[mt][0]), "r"(a[mt][1]), "r"(a[mt][2]), "r"(a[mt][3]),
                              "r"(b0), "r"(b1));
                    }
                }
            }

            __syncthreads();                    // everyone done reading current buffers
            // ---- store prefetched chunk into the other B buffer ----
            {
                int bufn = (kb + 1) & 1;
                #pragma unroll
                for (int t = 0; t < 4; t++) {
                    int idx = tid + t * 256;
                    int r = idx >> 3;
                    int c4 = idx & 7;
                    *(float4*)(dsm + BOFF + bufn * CHUNK_B + r * (LDH * 2) + c4 * 16) = pre[t];
                }
            }
            __syncthreads();
        }

        // ---- epilogue for this 128-col tile: per-row top-2 over the warp's 32 cols ----
        #pragma unroll
        for (int mt = 0; mt < 4; mt++) {
            #pragma unroll
            for (int rs = 0; rs < 2; rs++) {
                unsigned long long t0 = ~0ull, t1 = ~0ull;
                #pragma unroll
                for (int nt = 0; nt < 4; nt++) {
                    #pragma unroll
                    for (int cc = 0; cc < 2; cc++) {
                        int col = ct * 128 + wn * 32 + nt * 8 + 2 * tq + cc;
                        float d = fmaf(-2.0f, acc[mt][nt][rs * 2 + cc], s_cn[col]);
                        ins2(packkey(d, col), t0, t1);
                    }
                }
                // butterfly merge over the 4-thread quad (lanes g*4 + 0..3)
                #pragma unroll
                for (int off = 1; off <= 2; off <<= 1) {
                    unsigned long long o0 = __shfl_xor_sync(0xFFFFFFFFu, t0, off);
                    unsigned long long o1 = __shfl_xor_sync(0xFFFFFFFFu, t1, off);
                    unsigned long long n0 = t0 < o0 ? t0 : o0;
                    unsigned long long hi = t0 < o0 ? o0 : t0;
                    unsigned long long lo1 = t1 < o1 ? t1 : o1;
                    t0 = n0;
                    t1 = hi < lo1 ? hi : lo1;
                }
                if (mt == tq) { ins2(t0, rb0[rs], rb1[rs]); ins2(t1, rb0[rs], rb1[rs]); }
            }
        }
    }

    // ---- publish per-warp per-row top-2 ----
    #pragma unroll
    for (int rs = 0; rs < 2; rs++) {
        int row = wm * 64 + tq * 16 + g + 8 * rs;      // block-local row
        red[row * 8 + wn * 2 + 0] = rb0[rs];
        red[row * 8 + wn * 2 + 1] = rb1[rs];
    }
    __syncthreads();

    // ---- final per-row merge + margin filter + exact fp32 refine ----
    if (tid < 128) {
        int row = r0 + tid;
        unsigned long long kbest = ~0ull;
        #pragma unroll
        for (int i = 0; i < 8; i++) {
            unsigned long long v = red[tid * 8 + i];
            if (v < kbest) kbest = v;
        }
        float dmin = unpackd(kbest);
        float thr = dmin + MARGIN;
        int cols2[8], nc = 0;
        #pragma unroll
        for (int i = 0; i < 8; i++) {
            unsigned long long v = red[tid * 8 + i];
            if (unpackd(v) <= thr) cols2[nc++] = (int)(unsigned int)(v & 0xffffffffull);
        }

        int best;
        if (nc <= 1) {
            best = (int)(unsigned int)(kbest & 0xffffffffull);
        } else {
            float m2inv = -2.0f * g_invn[row];
            const float4* xr = (const float4*)(X + (size_t)row * DIM);
            unsigned long long bkey = ~0ull;
            for (int c = 0; c < nc; c++) {
                int col = cols2[c];
                const float4* cr = (const float4*)(C + (size_t)col * DIM);
                float s = 0.f;
                #pragma unroll 8
                for (int i = 0; i < 128; i++) {
                    float4 a = xr[i], b = cr[i];
                    s = fmaf(a.x, b.x, s); s = fmaf(a.y, b.y, s);
                    s = fmaf(a.z, b.z, s); s = fmaf(a.w, b.w, s);
                }
                float d = fmaf(m2inv, s, s_cn[col]);
                unsigned long long key = packkey(d, col);
                if (key < bkey) bkey = key;
            }
            best = (int)(unsigned int)(bkey & 0xffffffffull);
        }
        g_idx[row] = best;
        out[OFF_IDX + row] = (float)best;
        atomicAdd(&g_counts[best], 1.0f);
    }
}

// ================= kernel 3: quantized gather + dw scatter ========
__global__ void k_scatter(const float* __restrict__ X, const float* __restrict__ C,
                          float* __restrict__ out) {
    int row  = blockIdx.x * 8 + (threadIdx.x >> 5);
    int lane = threadIdx.x & 31;
    int k = g_idx[row];
    const float4* c4 = (const float4*)(C + (size_t)k * DIM);
    const float4* x4 = (const float4*)(X + (size_t)row * DIM);
    float4* q4 = (float4*)(out + OFF_Q + (size_t)row * DIM);
    float* dwr = g_dw + (size_t)k * DIM;
    #pragma unroll
    for (int i = lane; i < DIM / 4; i += 32) {
        q4[i] = c4[i];
        float4 v = x4[i];
        atomicAdd(dwr + i * 4 + 0, v.x);
        atomicAdd(dwr + i * 4 + 1, v.y);
        atomicAdd(dwr + i * 4 + 2, v.z);
        atomicAdd(dwr + i * 4 + 3, v.w);
    }
}

// ================= kernel 4: EMA cluster size =====================
__global__ void k_size(const float* __restrict__ ema_size, float* __restrict__ out) {
    __shared__ float s0[KC];
    __shared__ float part[1024];
    int tid = threadIdx.x;
    const float om = 1.0f - DECAYF;
    float local = 0.f;
    for (int k = tid; k < KC; k += 1024) {
        float v = ema_size[k] * DECAYF + om * g_counts[k];
        s0[k] = v;
        local += v;
    }
    part[tid] = local;
    __syncthreads();
    for (int o = 512; o > 0; o >>= 1) {
        if (tid < o) part[tid] += part[tid + o];
        __syncthreads();
    }
    float n = part[0];
    float denom = n + (float)KC * 1e-5f;
    for (int k = tid; k < KC; k += 1024) {
        float ns = (s0[k] + 1e-5f) / denom * n;
        out[OFF_NS + k] = ns;
        g_ns[k] = ns;
    }
}

// ================= kernel 5: new_w + new_centroids ================
__global__ void k_final(const float* __restrict__ ema_w, float* __restrict__ out) {
    int i = blockIdx.x * blockDim.x + threadIdx.x;
    int k = i >> 7;
    const float om = 1.0f - DECAYF;
    float4 w = ((const float4*)ema_w)[i];
    float4 d = ((const float4*)g_dw)[i];
    float4 nw;
    nw.x = w.x * DECAYF + om * d.x;
    nw.y = w.y * DECAYF + om * d.y;
    nw.z = w.z * DECAYF + om * d.z;
    nw.w = w.w * DECAYF + om * d.w;
    ((float4*)(out + OFF_NW))[i] = nw;
    float ns = __ldg(&g_ns[k]);
    float4 nc;
    nc.x = nw.x / ns;
    nc.y = nw.y / ns;
    nc.z = nw.z / ns;
    nc.w = nw.w / ns;
    ((float4*)(out + OFF_NC))[i] = nc;
}

// ================= launch ========================================
extern "C" void kernel_launch(void* const* d_in, const int* in_sizes, int n_in,
                              void* d_out, int out_size) {
    const float* X        = (const float*)d_in[0];
    const float* C        = (const float*)d_in[1];
    const float* ema_size = (const float*)d_in[2];
    const float* ema_w    = (const float*)d_in[3];
    float* out = (float*)d_out;

    cudaFuncSetAttribute(k_assign_mma, cudaFuncAttributeMaxDynamicSharedMemorySize, SMEM_DYN);

    k_zero      <<<(KC * DIM / 4) / 256, 256>>>();
    k_norms     <<<(KC + N_PTS) / 8, 256>>>(X, C);
    k_assign_mma<<<N_PTS / 128, 256, SMEM_DYN>>>(X, C, out);
    k_scatter   <<<N_PTS / 8, 256>>>(X, C, out);
    k_size      <<<1, 1024>>>(ema_size, out);
    k_final     <<<(KC * DIM / 4) / 256, 256>>>(ema_w, out);
}

// round 10
// speedup vs baseline: 2.5487x; 1.0082x over previous
#include <cuda_runtime.h>
#include <cuda_bf16.h>
#include <cstdint>

#define N_PTS 32768
#define DIM   512
#define KC    2048
#define DECAYF 0.99f
#define MARGIN 0.25f

// ---- output layout (float32, concat: quantized, indices, new_centroids, new_size, new_w) ----
#define OFF_Q   ((size_t)0)
#define OFF_IDX ((size_t)N_PTS * DIM)
#define OFF_NC  (OFF_IDX + N_PTS)
#define OFF_NS  (OFF_NC + (size_t)KC * DIM)
#define OFF_NW  (OFF_NS + KC)

// ---- scratch (device globals) ----
__device__ float g_cnorm2[KC];
__device__ float g_invn[N_PTS];
__device__ float g_dw[KC * DIM];
__device__ float g_counts[KC];
__device__ int   g_idx[N_PTS];
__device__ float g_ns[KC];
__device__ __nv_bfloat16 g_xn[(size_t)N_PTS * DIM];   // normalized X, bf16
__device__ __nv_bfloat16 g_cb[(size_t)KC * DIM];      // centroids, bf16

// ---- k_assign smem layout (bytes) ----
// A: 8 chunks x [128 rows x 128B (64 halves)] swizzled = 131072
// B: 4 stages x [128 rows x 128B]            = 65536  @ 131072
// cn: 2048 f32                               = 8192   @ 196608
// red: [128][8] u64                          = 8192   @ 204800
#define ACH       16384
#define AOFF      0
#define BOFF      131072
#define CNOFF     196608
#define REDOFF    204800
#define SMEM_DYN  212992

#define CP16(sm, gp)  asm volatile("cp.async.cg.shared.global [%0], [%1], 16;" :: "r"(sm), "l"(gp))
#define CP_COMMIT()   asm volatile("cp.async.commit_group;" ::: "memory")
#define CP_WAIT(n)    asm volatile("cp.async.wait_group %0;" :: "n"(n) : "memory")
#define LDSM_X4(r0,r1,r2,r3,ad) asm volatile( \
    "ldmatrix.sync.aligned.m8n8.x4.shared.b16 {%0,%1,%2,%3}, [%4];" \
    : "=r"(r0),"=r"(r1),"=r"(r2),"=r"(r3) : "r"(ad))

__device__ __forceinline__ unsigned long long packkey(float d, int col) {
    unsigned int u = __float_as_uint(d);
    u = (u & 0x80000000u) ? ~u : (u | 0x80000000u);
    return ((unsigned long long)u << 32) | (unsigned int)col;
}
__device__ __forceinline__ float unpackd(unsigned long long k) {
    unsigned int u = (unsigned int)(k >> 32);
    u = (u & 0x80000000u) ? (u ^ 0x80000000u) : ~u;
    return __uint_as_float(u);
}
__device__ __forceinline__ void ins2(unsigned long long v,
                                     unsigned long long& r0, unsigned long long& r1) {
    if (v < r0) { r1 = r0; r0 = v; } else if (v < r1) { r1 = v; }
}

// ================= kernel 0: zero scratch ============
__global__ void k_zero() {
    int i = blockIdx.x * blockDim.x + threadIdx.x;
    ((float4*)g_dw)[i] = make_float4(0.f, 0.f, 0.f, 0.f);
    if (i < KC) g_counts[i] = 0.f;
}

// ================= kernel 1: norms + bf16 conversion ==============
__global__ void k_norms(const float* __restrict__ X, const float* __restrict__ C) {
    int warp = (blockIdx.x * blockDim.x + threadIdx.x) >> 5;
    int lane = threadIdx.x & 31;
    if (warp < KC) {
        const float4* r = (const float4*)(C + (size_t)warp * DIM);
        float s = 0.f;
        float4 v[4];
        #pragma unroll
        for (int t = 0; t < 4; t++) {
            v[t] = r[lane + t * 32];
            s += v[t].x * v[t].x + v[t].y * v[t].y + v[t].z * v[t].z + v[t].w * v[t].w;
        }
        #pragma unroll
        for (int o = 16; o; o >>= 1) s += __shfl_xor_sync(0xFFFFFFFFu, s, o);
        if (lane == 0) g_cnorm2[warp] = s;
        __nv_bfloat162* ob = (__nv_bfloat162*)(g_cb + (size_t)warp * DIM);
        #pragma unroll
        for (int t = 0; t < 4; t++) {
            int i = lane + t * 32;
            ob[i * 2 + 0] = __floats2bfloat162_rn(v[t].x, v[t].y);
            ob[i * 2 + 1] = __floats2bfloat162_rn(v[t].z, v[t].w);
        }
    } else if (warp < KC + N_PTS) {
        int row = warp - KC;
        const float4* r = (const float4*)(X + (size_t)row * DIM);
        float s = 0.f;
        float4 v[4];
        #pragma unroll
        for (int t = 0; t < 4; t++) {
            v[t] = r[lane + t * 32];
            s += v[t].x * v[t].x + v[t].y * v[t].y + v[t].z * v[t].z + v[t].w * v[t].w;
        }
        #pragma unroll
        for (int o = 16; o; o >>= 1) s += __shfl_xor_sync(0xFFFFFFFFu, s, o);
        float in = 1.0f / fmaxf(sqrtf(s), 1e-12f);
        if (lane == 0) g_invn[row] = in;
        __nv_bfloat162* ob = (__nv_bfloat162*)(g_xn + (size_t)row * DIM);
        #pragma unroll
        for (int t = 0; t < 4; t++) {
            int i = lane + t * 32;
            ob[i * 2 + 0] = __floats2bfloat162_rn(v[t].x * in, v[t].y * in);
            ob[i * 2 + 1] = __floats2bfloat162_rn(v[t].z * in, v[t].w * in);
        }
    }
}

// ================= kernel 2: HMMA GEMM (ldmatrix + 4-stage cp.async pipeline) ============
// 512 threads = 16 warps in 4x4 grid; warp tile 32x32; block tile 128 rows x 128 cols.
__global__ __launch_bounds__(512, 1) void k_assign_mma(const float* __restrict__ X,
                                                       const float* __restrict__ C,
                                                       float* __restrict__ out) {
    extern __shared__ char dsm[];
    float* s_cn = (float*)(dsm + CNOFF);
    unsigned long long* red = (unsigned long long*)(dsm + REDOFF);
    const uint32_t sbase = (uint32_t)__cvta_generic_to_shared(dsm);

    const int tid = threadIdx.x;
    const int lane = tid & 31;
    const int wid = tid >> 5;
    const int wm = wid >> 2;          // warp row strip (0..3), 32 rows
    const int wn = wid & 3;           // warp col strip (0..3), 32 cols
    const int g = lane >> 2;          // 0..7
    const int tq = lane & 3;          // 0..3
    const int r0 = blockIdx.x * 128;

    // ---- A preload: 8 chunks of [128r x 64 halves], swizzled seg^(r&7), via cp.async ----
    // commit-group 0
    {
        const char* xb = (const char*)(g_xn + (size_t)r0 * DIM);
        #pragma unroll
        for (int t = 0; t < 16; t++) {
            int idx = tid + t * 512;              // 8192 16B segments
            int chunk = idx >> 10;
            int r = (idx >> 3) & 127;
            int s = idx & 7;
            const char* gp = xb + ((size_t)r * DIM + chunk * 64 + s * 8) * 2;
            uint32_t sp = sbase + AOFF + chunk * ACH + r * 128 + ((s ^ (r & 7)) * 16);
            CP16(sp, gp);
        }
        CP_COMMIT();
    }
    // ---- centroid norms ----
    for (int i = tid; i < KC; i += 512) s_cn[i] = g_cnorm2[i];

    // ---- B pipeline prologue: chunks 0,1,2 -> commit-groups 1,2,3 ----
    #pragma unroll
    for (int pc = 0; pc < 3; pc++) {
        const char* cb = (const char*)g_cb;
        #pragma unroll
        for (int t = 0; t < 2; t++) {
            int idx = tid + t * 512;              // 1024 segments
            int r = idx >> 3;
            int s = idx & 7;
            const char* gp = cb + ((size_t)r * DIM + pc * 64 + s * 8) * 2;   // ct=0
            uint32_t sp = sbase + BOFF + pc * ACH + r * 128 + ((s ^ (r & 7)) * 16);
            CP16(sp, gp);
        }
        CP_COMMIT();
    }

    unsigned long long rb0 = ~0ull, rb1 = ~0ull;   // top-2 for this thread's owned row
    float acc[2][4][4];

    for (int ct = 0; ct < 16; ++ct) {
        #pragma unroll
        for (int mt = 0; mt < 2; mt++)
            #pragma unroll
            for (int nt = 0; nt < 4; nt++)
                #pragma unroll
                for (int c = 0; c < 4; c++) acc[mt][nt][c] = 0.f;

        for (int kb = 0; kb < 8; ++kb) {
            const int ci = ct * 8 + kb;
            // chunk ci is commit-group ci+1; committed so far: 0..ci+3.
            // wait_group 2 -> groups 0..ci+1 complete -> chunk ci ready (own copies).
            CP_WAIT(2);
            // barrier: (a) publishes ALL threads' copies of chunk ci,
            //          (b) all warps done reading stage (ci-1)&3 from iter ci-1,
            //              so it is safe to overwrite it below with chunk ci+3.
            __syncthreads();

            if (ci + 3 < 128) {
                int ct2 = (ci + 3) >> 3, kb2 = (ci + 3) & 7;
                const char* cb = (const char*)(g_cb + (size_t)ct2 * 128 * DIM);
                int st = (ci + 3) & 3;
                #pragma unroll
                for (int t = 0; t < 2; t++) {
                    int idx = tid + t * 512;
                    int r = idx >> 3;
                    int s = idx & 7;
                    const char* gp = cb + ((size_t)r * DIM + kb2 * 64 + s * 8) * 2;
                    uint32_t sp = sbase + BOFF + st * ACH + r * 128 + ((s ^ (r & 7)) * 16);
                    CP16(sp, gp);
                }
            }
            CP_COMMIT();                  // commit every iter (possibly empty) for uniform counting

            // ---- MMA on A chunk kb, B stage ci&3 ----
            const uint32_t Ab = sbase + AOFF + kb * ACH;
            const uint32_t Bb = sbase + BOFF + (ci & 3) * ACH;
            #pragma unroll
            for (int ks = 0; ks < 4; ks++) {
                uint32_t a[2][4];
                #pragma unroll
                for (int mt = 0; mt < 2; mt++) {
                    int r = wm * 32 + mt * 16 + (lane & 15);
                    int s = ks * 2 + (lane >> 4);
                    uint32_t ad = Ab + r * 128 + ((s ^ (r & 7)) * 16);
                    LDSM_X4(a[mt][0], a[mt][1], a[mt][2], a[mt][3], ad);
                }
                uint32_t b[4][2];
                #pragma unroll
                for (int ntp = 0; ntp < 2; ntp++) {
                    int r = wn * 32 + ntp * 16 + (lane & 15);
                    int s = ks * 2 + (lane >> 4);
                    uint32_t ad = Bb + r * 128 + ((s ^ (r & 7)) * 16);
                    uint32_t q0, q1, q2, q3;
                    LDSM_X4(q0, q1, q2, q3, ad);
                    b[ntp * 2 + 0][0] = q0; b[ntp * 2 + 0][1] = q2;
                    b[ntp * 2 + 1][0] = q1; b[ntp * 2 + 1][1] = q3;
                }
                #pragma unroll
                for (int mt = 0; mt < 2; mt++)
                    #pragma unroll
                    for (int nt = 0; nt < 4; nt++) {
                        asm volatile(
                            "mma.sync.aligned.m16n8k16.row.col.f32.bf16.bf16.f32 "
                            "{%0,%1,%2,%3}, {%4,%5,%6,%7}, {%8,%9}, {%0,%1,%2,%3};"
                            : "+f"(acc[mt][nt][0]), "+f"(acc[mt][nt][1]),
                              "+f"(acc[mt][nt][2]), "+f"(acc[mt][nt][3])
                            : "r"(a[mt][0]), "r"(a[mt][1]), "r"(a[mt][2]), "r"(a[mt][3]),
                              "r"(b[nt][0]), "r"(b[nt][1]));
                    }
            }
        }

        // ---- epilogue: per (mt,rs) quad-exact top-2 over warp's 32 cols, owner keeps ----
        #pragma unroll
        for (int mt = 0; mt < 2; mt++) {
            #pragma unroll
            for (int rs = 0; rs < 2; rs++) {
                unsigned long long t0 = ~0ull, t1 = ~0ull;
                #pragma unroll
                for (int nt = 0; nt < 4; nt++) {
                    #pragma unroll
                    for (int cc = 0; cc < 2; cc++) {
                        int col = ct * 128 + wn * 32 + nt * 8 + 2 * tq + cc;
                        float d = fmaf(-2.0f, acc[mt][nt][rs * 2 + cc], s_cn[col]);
                        ins2(packkey(d, col), t0, t1);
                    }
                }
                #pragma unroll
                for (int off = 1; off <= 2; off <<= 1) {
                    unsigned long long o0 = __shfl_xor_sync(0xFFFFFFFFu, t0, off);
                    unsigned long long o1 = __shfl_xor_sync(0xFFFFFFFFu, t1, off);
                    unsigned long long n0 = t0 < o0 ? t0 : o0;
                    unsigned long long hi = t0 < o0 ? o0 : t0;
                    unsigned long long lo1 = t1 < o1 ? t1 : o1;
                    t0 = n0;
                    t1 = hi < lo1 ? hi : lo1;
                }
                if (tq == mt * 2 + rs) { ins2(t0, rb0, rb1); ins2(t1, rb0, rb1); }
            }
        }
    }

    // ---- publish per-warp top-2; owned row = wm*32 + (tq>>1)*16 + g + 8*(tq&1) ----
    {
        int row = wm * 32 + (tq >> 1) * 16 + g + 8 * (tq & 1);
        red[row * 8 + wn * 2 + 0] = rb0;
        red[row * 8 + wn * 2 + 1] = rb1;
    }
    __syncthreads();

    // ---- final merge + margin filter + exact fp32 refine ----
    if (tid < 128) {
        int row = r0 + tid;
        unsigned long long kbest = ~0ull;
        #pragma unroll
        for (int i = 0; i < 8; i++) {
            unsigned long long v = red[tid * 8 + i];
            if (v < kbest) kbest = v;
        }
        float thr = unpackd(kbest) + MARGIN;
        int cols2[8], nc = 0;
        #pragma unroll
        for (int i = 0; i < 8; i++) {
            unsigned long long v = red[tid * 8 + i];
            if (unpackd(v) <= thr) cols2[nc++] = (int)(unsigned int)(v & 0xffffffffull);
        }

        int best;
        if (nc <= 1) {
            best = (int)(unsigned int)(kbest & 0xffffffffull);
        } else {
            float m2inv = -2.0f * g_invn[row];
            const float4* xr = (const float4*)(X + (size_t)row * DIM);
            unsigned long long bkey = ~0ull;
            for (int c = 0; c < nc; c++) {
                int col = cols2[c];
                const float4* cr = (const float4*)(C + (size_t)col * DIM);
                float s = 0.f;
                #pragma unroll 8
                for (int i = 0; i < 128; i++) {
                    float4 a = xr[i], b = cr[i];
                    s = fmaf(a.x, b.x, s); s = fmaf(a.y, b.y, s);
                    s = fmaf(a.z, b.z, s); s = fmaf(a.w, b.w, s);
                }
                float d = fmaf(m2inv, s, s_cn[col]);
                unsigned long long key = packkey(d, col);
                if (key < bkey) bkey = key;
            }
            best = (int)(unsigned int)(bkey & 0xffffffffull);
        }
        g_idx[row] = best;
        out[OFF_IDX + row] = (float)best;
        atomicAdd(&g_counts[best], 1.0f);
    }
}

// ================= kernel 3: quantized gather + dw scatter ========
__global__ void k_scatter(const float* __restrict__ X, const float* __restrict__ C,
                          float* __restrict__ out) {
    int row  = blockIdx.x * 8 + (threadIdx.x >> 5);
    int lane = threadIdx.x & 31;
    int k = g_idx[row];
    const float4* c4 = (const float4*)(C + (size_t)k * DIM);
    const float4* x4 = (const float4*)(X + (size_t)row * DIM);
    float4* q4 = (float4*)(out + OFF_Q + (size_t)row * DIM);
    float* dwr = g_dw + (size_t)k * DIM;
    #pragma unroll
    for (int i = lane; i < DIM / 4; i += 32) {
        q4[i] = c4[i];
        float4 v = x4[i];
        atomicAdd(dwr + i * 4 + 0, v.x);
        atomicAdd(dwr + i * 4 + 1, v.y);
        atomicAdd(dwr + i * 4 + 2, v.z);
        atomicAdd(dwr + i * 4 + 3, v.w);
    }
}

// ================= kernel 4: EMA cluster size =====================
__global__ void k_size(const float* __restrict__ ema_size, float* __restrict__ out) {
    __shared__ float s0[KC];
    __shared__ float part[1024];
    int tid = threadIdx.x;
    const float om = 1.0f - DECAYF;
    float local = 0.f;
    for (int k = tid; k < KC; k += 1024) {
        float v = ema_size[k] * DECAYF + om * g_counts[k];
        s0[k] = v;
        local += v;
    }
    part[tid] = local;
    __syncthreads();
    for (int o = 512; o > 0; o >>= 1) {
        if (tid < o) part[tid] += part[tid + o];
        __syncthreads();
    }
    float n = part[0];
    float denom = n + (float)KC * 1e-5f;
    for (int k = tid; k < KC; k += 1024) {
        float ns = (s0[k] + 1e-5f) / denom * n;
        out[OFF_NS + k] = ns;
        g_ns[k] = ns;
    }
}

// ================= kernel 5: new_w + new_centroids ================
__global__ void k_final(const float* __restrict__ ema_w, float* __restrict__ out) {
    int i = blockIdx.x * blockDim.x + threadIdx.x;
    int k = i >> 7;
    const float om = 1.0f - DECAYF;
    float4 w = ((const float4*)ema_w)[i];
    float4 d = ((const float4*)g_dw)[i];
    float4 nw;
    nw.x = w.x * DECAYF + om * d.x;
    nw.y = w.y * DECAYF + om * d.y;
    nw.z = w.z * DECAYF + om * d.z;
    nw.w = w.w * DECAYF + om * d.w;
    ((float4*)(out + OFF_NW))[i] = nw;
    float ns = __ldg(&g_ns[k]);
    float4 nc;
    nc.x = nw.x / ns;
    nc.y = nw.y / ns;
    nc.z = nw.z / ns;
    nc.w = nw.w / ns;
    ((float4*)(out + OFF_NC))[i] = nc;
}

// ================= launch ========================================
extern "C" void kernel_launch(void* const* d_in, const int* in_sizes, int n_in,
                              void* d_out, int out_size) {
    const float* X        = (const float*)d_in[0];
    const float* C        = (const float*)d_in[1];
    const float* ema_size = (const float*)d_in[2];
    const float* ema_w    = (const float*)d_in[3];
    float* out = (float*)d_out;

    cudaFuncSetAttribute(k_assign_mma, cudaFuncAttributeMaxDynamicSharedMemorySize, SMEM_DYN);

    k_zero      <<<(KC * DIM / 4) / 256, 256>>>();
    k_norms     <<<(KC + N_PTS) / 8, 256>>>(X, C);
    k_assign_mma<<<N_PTS / 128, 512, SMEM_DYN>>>(X, C, out);
    k_scatter   <<<N_PTS / 8, 256>>>(X, C, out);
    k_size      <<<1, 1024>>>(ema_size, out);
    k_final     <<<(KC * DIM / 4) / 256, 256>>>(ema_w, out);
}

// round 11
// speedup vs baseline: 2.5523x; 1.0014x over previous
#include <cuda_runtime.h>
#include <cuda_fp16.h>
#include <cstdint>

#define N_PTS 32768
#define DIM   512
#define KC    2048
#define DECAYF 0.99f
#define MARGIN 0.25f

// ---- output layout (float32, concat: quantized, indices, new_centroids, new_size, new_w) ----
#define OFF_Q   ((size_t)0)
#define OFF_IDX ((size_t)N_PTS * DIM)
#define OFF_NC  (OFF_IDX + N_PTS)
#define OFF_NS  (OFF_NC + (size_t)KC * DIM)
#define OFF_NW  (OFF_NS + KC)

// ---- scratch (device globals) ----
__device__ float g_cnorm2[KC];
__device__ float g_invn[N_PTS];
__device__ float g_dw[KC * DIM];
__device__ float g_counts[KC];
__device__ int   g_idx[N_PTS];
__device__ float g_ns[KC];
__device__ __half g_xn[(size_t)N_PTS * DIM];   // normalized X, fp16
__device__ __half g_cb[(size_t)KC * DIM];      // centroids, fp16

// ---- k_assign smem layout (bytes) ----
#define ACH       16384
#define AOFF      0
#define BOFF      131072
#define CNOFF     196608
#define REDOFF    204800
#define SMEM_DYN  212992

#define CP16(sm, gp)  asm volatile("cp.async.cg.shared.global [%0], [%1], 16;" :: "r"(sm), "l"(gp))
#define CP_COMMIT()   asm volatile("cp.async.commit_group;" ::: "memory")
#define CP_WAIT(n)    asm volatile("cp.async.wait_group %0;" :: "n"(n) : "memory")
#define LDSM_X4(r0,r1,r2,r3,ad) asm volatile( \
    "ldmatrix.sync.aligned.m8n8.x4.shared.b16 {%0,%1,%2,%3}, [%4];" \
    : "=r"(r0),"=r"(r1),"=r"(r2),"=r"(r3) : "r"(ad))

__device__ __forceinline__ unsigned long long packkey(float d, int col) {
    unsigned int u = __float_as_uint(d);
    u = (u & 0x80000000u) ? ~u : (u | 0x80000000u);
    return ((unsigned long long)u << 32) | (unsigned int)col;
}
__device__ __forceinline__ float unpackd(unsigned long long k) {
    unsigned int u = (unsigned int)(k >> 32);
    u = (u & 0x80000000u) ? (u ^ 0x80000000u) : ~u;
    return __uint_as_float(u);
}
__device__ __forceinline__ void ins2(unsigned long long v,
                                     unsigned long long& r0, unsigned long long& r1) {
    if (v < r0) { r1 = r0; r0 = v; } else if (v < r1) { r1 = v; }
}

// ================= kernel 0: zero scratch ============
__global__ void k_zero() {
    int i = blockIdx.x * blockDim.x + threadIdx.x;
    ((float4*)g_dw)[i] = make_float4(0.f, 0.f, 0.f, 0.f);
    if (i < KC) g_counts[i] = 0.f;
}

// ================= kernel 1: norms + fp16 conversion ==============
__global__ void k_norms(const float* __restrict__ X, const float* __restrict__ C) {
    int warp = (blockIdx.x * blockDim.x + threadIdx.x) >> 5;
    int lane = threadIdx.x & 31;
    if (warp < KC) {
        const float4* r = (const float4*)(C + (size_t)warp * DIM);
        float s = 0.f;
        float4 v[4];
        #pragma unroll
        for (int t = 0; t < 4; t++) {
            v[t] = r[lane + t * 32];
            s += v[t].x * v[t].x + v[t].y * v[t].y + v[t].z * v[t].z + v[t].w * v[t].w;
        }
        #pragma unroll
        for (int o = 16; o; o >>= 1) s += __shfl_xor_sync(0xFFFFFFFFu, s, o);
        if (lane == 0) g_cnorm2[warp] = s;
        __half2* ob = (__half2*)(g_cb + (size_t)warp * DIM);
        #pragma unroll
        for (int t = 0; t < 4; t++) {
            int i = lane + t * 32;
            ob[i * 2 + 0] = __floats2half2_rn(v[t].x, v[t].y);
            ob[i * 2 + 1] = __floats2half2_rn(v[t].z, v[t].w);
        }
    } else if (warp < KC + N_PTS) {
        int row = warp - KC;
        const float4* r = (const float4*)(X + (size_t)row * DIM);
        float s = 0.f;
        float4 v[4];
        #pragma unroll
        for (int t = 0; t < 4; t++) {
            v[t] = r[lane + t * 32];
            s += v[t].x * v[t].x + v[t].y * v[t].y + v[t].z * v[t].z + v[t].w * v[t].w;
        }
        #pragma unroll
        for (int o = 16; o; o >>= 1) s += __shfl_xor_sync(0xFFFFFFFFu, s, o);
        float in = 1.0f / fmaxf(sqrtf(s), 1e-12f);
        if (lane == 0) g_invn[row] = in;
        __half2* ob = (__half2*)(g_xn + (size_t)row * DIM);
        #pragma unroll
        for (int t = 0; t < 4; t++) {
            int i = lane + t * 32;
            ob[i * 2 + 0] = __floats2half2_rn(v[t].x * in, v[t].y * in);
            ob[i * 2 + 1] = __floats2half2_rn(v[t].z * in, v[t].w * in);
        }
    }
}

// ================= kernel 2: fp16 HMMA GEMM (ldmatrix + 4-stage cp.async) ============
__global__ __launch_bounds__(512, 1) void k_assign_mma(const float* __restrict__ X,
                                                       const float* __restrict__ C,
                                                       float* __restrict__ out) {
    extern __shared__ char dsm[];
    float* s_cn = (float*)(dsm + CNOFF);
    unsigned long long* red = (unsigned long long*)(dsm + REDOFF);
    const uint32_t sbase = (uint32_t)__cvta_generic_to_shared(dsm);

    const int tid = threadIdx.x;
    const int lane = tid & 31;
    const int wid = tid >> 5;
    const int wm = wid >> 2;
    const int wn = wid & 3;
    const int g = lane >> 2;
    const int tq = lane & 3;
    const int r0 = blockIdx.x * 128;

    // ---- A preload: commit-group 0 ----
    {
        const char* xb = (const char*)(g_xn + (size_t)r0 * DIM);
        #pragma unroll
        for (int t = 0; t < 16; t++) {
            int idx = tid + t * 512;
            int chunk = idx >> 10;
            int r = (idx >> 3) & 127;
            int s = idx & 7;
            const char* gp = xb + ((size_t)r * DIM + chunk * 64 + s * 8) * 2;
            uint32_t sp = sbase + AOFF + chunk * ACH + r * 128 + ((s ^ (r & 7)) * 16);
            CP16(sp, gp);
        }
        CP_COMMIT();
    }
    for (int i = tid; i < KC; i += 512) s_cn[i] = g_cnorm2[i];

    // ---- B prologue: chunks 0,1,2 -> groups 1,2,3 ----
    #pragma unroll
    for (int pc = 0; pc < 3; pc++) {
        const char* cb = (const char*)g_cb;
        #pragma unroll
        for (int t = 0; t < 2; t++) {
            int idx = tid + t * 512;
            int r = idx >> 3;
            int s = idx & 7;
            const char* gp = cb + ((size_t)r * DIM + pc * 64 + s * 8) * 2;
            uint32_t sp = sbase + BOFF + pc * ACH + r * 128 + ((s ^ (r & 7)) * 16);
            CP16(sp, gp);
        }
        CP_COMMIT();
    }

    unsigned long long rb0 = ~0ull, rb1 = ~0ull;
    float acc[2][4][4];

    for (int ct = 0; ct < 16; ++ct) {
        #pragma unroll
        for (int mt = 0; mt < 2; mt++)
            #pragma unroll
            for (int nt = 0; nt < 4; nt++)
                #pragma unroll
                for (int c = 0; c < 4; c++) acc[mt][nt][c] = 0.f;

        for (int kb = 0; kb < 8; ++kb) {
            const int ci = ct * 8 + kb;
            CP_WAIT(2);
            __syncthreads();

            if (ci + 3 < 128) {
                int ct2 = (ci + 3) >> 3, kb2 = (ci + 3) & 7;
                const char* cb = (const char*)(g_cb + (size_t)ct2 * 128 * DIM);
                int st = (ci + 3) & 3;
                #pragma unroll
                for (int t = 0; t < 2; t++) {
                    int idx = tid + t * 512;
                    int r = idx >> 3;
                    int s = idx & 7;
                    const char* gp = cb + ((size_t)r * DIM + kb2 * 64 + s * 8) * 2;
                    uint32_t sp = sbase + BOFF + st * ACH + r * 128 + ((s ^ (r & 7)) * 16);
                    CP16(sp, gp);
                }
            }
            CP_COMMIT();

            const uint32_t Ab = sbase + AOFF + kb * ACH;
            const uint32_t Bb = sbase + BOFF + (ci & 3) * ACH;
            #pragma unroll
            for (int ks = 0; ks < 4; ks++) {
                uint32_t a[2][4];
                #pragma unroll
                for (int mt = 0; mt < 2; mt++) {
                    int r = wm * 32 + mt * 16 + (lane & 15);
                    int s = ks * 2 + (lane >> 4);
                    uint32_t ad = Ab + r * 128 + ((s ^ (r & 7)) * 16);
                    LDSM_X4(a[mt][0], a[mt][1], a[mt][2], a[mt][3], ad);
                }
                uint32_t b[4][2];
                #pragma unroll
                for (int ntp = 0; ntp < 2; ntp++) {
                    int r = wn * 32 + ntp * 16 + (lane & 15);
                    int s = ks * 2 + (lane >> 4);
                    uint32_t ad = Bb + r * 128 + ((s ^ (r & 7)) * 16);
                    uint32_t q0, q1, q2, q3;
                    LDSM_X4(q0, q1, q2, q3, ad);
                    b[ntp * 2 + 0][0] = q0; b[ntp * 2 + 0][1] = q2;
                    b[ntp * 2 + 1][0] = q1; b[ntp * 2 + 1][1] = q3;
                }
                #pragma unroll
                for (int mt = 0; mt < 2; mt++)
                    #pragma unroll
                    for (int nt = 0; nt < 4; nt++) {
                        asm volatile(
                            "mma.sync.aligned.m16n8k16.row.col.f32.f16.f16.f32 "
                            "{%0,%1,%2,%3}, {%4,%5,%6,%7}, {%8,%9}, {%0,%1,%2,%3};"
                            : "+f"(acc[mt][nt][0]), "+f"(acc[mt][nt][1]),
                              "+f"(acc[mt][nt][2]), "+f"(acc[mt][nt][3])
                            : "r"(a[mt][0]), "r"(a[mt][1]), "r"(a[mt][2]), "r"(a[mt][3]),
                              "r"(b[nt][0]), "r"(b[nt][1]));
                    }
            }
        }

        // ---- epilogue ----
        #pragma unroll
        for (int mt = 0; mt < 2; mt++) {
            #pragma unroll
            for (int rs = 0; rs < 2; rs++) {
                unsigned long long t0 = ~0ull, t1 = ~0ull;
                #pragma unroll
                for (int nt = 0; nt < 4; nt++) {
                    #pragma unroll
                    for (int cc = 0; cc < 2; cc++) {
                        int col = ct * 128 + wn * 32 + nt * 8 + 2 * tq + cc;
                        float d = fmaf(-2.0f, acc[mt][nt][rs * 2 + cc], s_cn[col]);
                        ins2(packkey(d, col), t0, t1);
                    }
                }
                #pragma unroll
                for (int off = 1; off <= 2; off <<= 1) {
                    unsigned long long o0 = __shfl_xor_sync(0xFFFFFFFFu, t0, off);
                    unsigned long long o1 = __shfl_xor_sync(0xFFFFFFFFu, t1, off);
                    unsigned long long n0 = t0 < o0 ? t0 : o0;
                    unsigned long long hi = t0 < o0 ? o0 : t0;
                    unsigned long long lo1 = t1 < o1 ? t1 : o1;
                    t0 = n0;
                    t1 = hi < lo1 ? hi : lo1;
                }
                if (tq == mt * 2 + rs) { ins2(t0, rb0, rb1); ins2(t1, rb0, rb1); }
            }
        }
    }

    {
        int row = wm * 32 + (tq >> 1) * 16 + g + 8 * (tq & 1);
        red[row * 8 + wn * 2 + 0] = rb0;
        red[row * 8 + wn * 2 + 1] = rb1;
    }
    __syncthreads();

    if (tid < 128) {
        int row = r0 + tid;
        unsigned long long kbest = ~0ull;
        #pragma unroll
        for (int i = 0; i < 8; i++) {
            unsigned long long v = red[tid * 8 + i];
            if (v < kbest) kbest = v;
        }
        float thr = unpackd(kbest) + MARGIN;
        int cols2[8], nc = 0;
        #pragma unroll
        for (int i = 0; i < 8; i++) {
            unsigned long long v = red[tid * 8 + i];
            if (unpackd(v) <= thr) cols2[nc++] = (int)(unsigned int)(v & 0xffffffffull);
        }

        int best;
        if (nc <= 1) {
            best = (int)(unsigned int)(kbest & 0xffffffffull);
        } else {
            float m2inv = -2.0f * g_invn[row];
            const float4* xr = (const float4*)(X + (size_t)row * DIM);
            unsigned long long bkey = ~0ull;
            for (int c = 0; c < nc; c++) {
                int col = cols2[c];
                const float4* cr = (const float4*)(C + (size_t)col * DIM);
                float s = 0.f;
                #pragma unroll 8
                for (int i = 0; i < 128; i++) {
                    float4 a = xr[i], b = cr[i];
                    s = fmaf(a.x, b.x, s); s = fmaf(a.y, b.y, s);
                    s = fmaf(a.z, b.z, s); s = fmaf(a.w, b.w, s);
                }
                float d = fmaf(m2inv, s, s_cn[col]);
                unsigned long long key = packkey(d, col);
                if (key < bkey) bkey = key;
            }
            best = (int)(unsigned int)(bkey & 0xffffffffull);
        }
        g_idx[row] = best;
        out[OFF_IDX + row] = (float)best;
        atomicAdd(&g_counts[best], 1.0f);
    }
}

// ================= kernel 3: quantized gather + dw scatter ========
__global__ void k_scatter(const float* __restrict__ X, const float* __restrict__ C,
                          float* __restrict__ out) {
    int row  = blockIdx.x * 8 + (threadIdx.x >> 5);
    int lane = threadIdx.x & 31;
    int k = g_idx[row];
    const float4* c4 = (const float4*)(C + (size_t)k * DIM);
    const float4* x4 = (const float4*)(X + (size_t)row * DIM);
    float4* q4 = (float4*)(out + OFF_Q + (size_t)row * DIM);
    float* dwr = g_dw + (size_t)k * DIM;
    #pragma unroll
    for (int i = lane; i < DIM / 4; i += 32) {
        q4[i] = c4[i];
        float4 v = x4[i];
        atomicAdd(dwr + i * 4 + 0, v.x);
        atomicAdd(dwr + i * 4 + 1, v.y);
        atomicAdd(dwr + i * 4 + 2, v.z);
        atomicAdd(dwr + i * 4 + 3, v.w);
    }
}

// ================= kernel 4: EMA cluster size =====================
__global__ void k_size(const float* __restrict__ ema_size, float* __restrict__ out) {
    __shared__ float s0[KC];
    __shared__ float part[1024];
    int tid = threadIdx.x;
    const float om = 1.0f - DECAYF;
    float local = 0.f;
    for (int k = tid; k < KC; k += 1024) {
        float v = ema_size[k] * DECAYF + om * g_counts[k];
        s0[k] = v;
        local += v;
    }
    part[tid] = local;
    __syncthreads();
    for (int o = 512; o > 0; o >>= 1) {
        if (tid < o) part[tid] += part[tid + o];
        __syncthreads();
    }
    float n = part[0];
    float denom = n + (float)KC * 1e-5f;
    for (int k = tid; k < KC; k += 1024) {
        float ns = (s0[k] + 1e-5f) / denom * n;
        out[OFF_NS + k] = ns;
        g_ns[k] = ns;
    }
}

// ================= kernel 5: new_w + new_centroids ================
__global__ void k_final(const float* __restrict__ ema_w, float* __restrict__ out) {
    int i = blockIdx.x * blockDim.x + threadIdx.x;
    int k = i >> 7;
    const float om = 1.0f - DECAYF;
    float4 w = ((const float4*)ema_w)[i];
    float4 d = ((const float4*)g_dw)[i];
    float4 nw;
    nw.x = w.x * DECAYF + om * d.x;
    nw.y = w.y * DECAYF + om * d.y;
    nw.z = w.z * DECAYF + om * d.z;
    nw.w = w.w * DECAYF + om * d.w;
    ((float4*)(out + OFF_NW))[i] = nw;
    float ns = __ldg(&g_ns[k]);
    float4 nc;
    nc.x = nw.x / ns;
    nc.y = nw.y / ns;
    nc.z = nw.z / ns;
    nc.w = nw.w / ns;
    ((float4*)(out + OFF_NC))[i] = nc;
}

// ================= launch ========================================
extern "C" void kernel_launch(void* const* d_in, const int* in_sizes, int n_in,
                              void* d_out, int out_size) {
    const float* X        = (const float*)d_in[0];
    const float* C        = (const float*)d_in[1];
    const float* ema_size = (const float*)d_in[2];
    const float* ema_w    = (const float*)d_in[3];
    float* out = (float*)d_out;

    cudaFuncSetAttribute(k_assign_mma, cudaFuncAttributeMaxDynamicSharedMemorySize, SMEM_DYN);

    k_zero      <<<(KC * DIM / 4) / 256, 256>>>();
    k_norms     <<<(KC + N_PTS) / 8, 256>>>(X, C);
    k_assign_mma<<<N_PTS / 128, 512, SMEM_DYN>>>(X, C, out);
    k_scatter   <<<N_PTS / 8, 256>>>(X, C, out);
    k_size      <<<1, 1024>>>(ema_size, out);
    k_final     <<<(KC * DIM / 4) / 256, 256>>>(ema_w, out);
}

// round 14
// speedup vs baseline: 2.5703x; 1.0070x over previous
#include <cuda_runtime.h>
#include <cuda_fp8.h>
#include <cstdint>

#define N_PTS 32768
#define DIM   512
#define KC    2048
#define DECAYF 0.99f
#define MARGIN 1.0f
#define QSCALE 16.0f

// ---- output layout (float32, concat: quantized, indices, new_centroids, new_size, new_w) ----
#define OFF_Q   ((size_t)0)
#define OFF_IDX ((size_t)N_PTS * DIM)
#define OFF_NC  (OFF_IDX + N_PTS)
#define OFF_NS  (OFF_NC + (size_t)KC * DIM)
#define OFF_NW  (OFF_NS + KC)

// ---- scratch (device globals) ----
__device__ float g_cnorm2[KC];
__device__ float g_invn[N_PTS];
__device__ float g_dw[KC * DIM];
__device__ float g_counts[KC];
__device__ int   g_idx[N_PTS];
__device__ float g_ns[KC];
__device__ unsigned char g_xq[(size_t)N_PTS * DIM];   // e4m3(16 * xn)
__device__ unsigned char g_cq[(size_t)KC * DIM];      // e4m3(16 * c)

// ---- k_assign smem layout (bytes) ----
// A: 4 chunks x [128 rows x 128B (128 fp8)] = 65536
// B: 4 stages x [128 rows x 128B]           = 65536 @ 65536
// cn: 2048 f32 = 8192  @ 131072 ; red: [128][8] u64 = 8192 @ 139264
#define ACH       16384
#define AOFF      0
#define BOFF      65536
#define CNOFF     131072
#define REDOFF    139264
#define SMEM_DYN  147456

#define CP16(sm, gp)  asm volatile("cp.async.cg.shared.global [%0], [%1], 16;" :: "r"(sm), "l"(gp))
#define CP_COMMIT()   asm volatile("cp.async.commit_group;" ::: "memory")
#define CP_WAIT(n)    asm volatile("cp.async.wait_group %0;" :: "n"(n) : "memory")
#define LDSM_X4(r0,r1,r2,r3,ad) asm volatile( \
    "ldmatrix.sync.aligned.m8n8.x4.shared.b16 {%0,%1,%2,%3}, [%4];" \
    : "=r"(r0),"=r"(r1),"=r"(r2),"=r"(r3) : "r"(ad))

__device__ __forceinline__ uint32_t pack4_e4m3(float a, float b, float c, float d) {
    uint32_t lo = (uint32_t)__nv_cvt_float2_to_fp8x2(make_float2(a, b), __NV_SATFINITE, __NV_E4M3);
    uint32_t hi = (uint32_t)__nv_cvt_float2_to_fp8x2(make_float2(c, d), __NV_SATFINITE, __NV_E4M3);
    return lo | (hi << 16);
}

__device__ __forceinline__ unsigned long long packkey(float d, int col) {
    unsigned int u = __float_as_uint(d);
    u = (u & 0x80000000u) ? ~u : (u | 0x80000000u);
    return ((unsigned long long)u << 32) | (unsigned int)col;
}
__device__ __forceinline__ float unpackd(unsigned long long k) {
    unsigned int u = (unsigned int)(k >> 32);
    u = (u & 0x80000000u) ? (u ^ 0x80000000u) : ~u;
    return __uint_as_float(u);
}
__device__ __forceinline__ void ins2(unsigned long long v,
                                     unsigned long long& r0, unsigned long long& r1) {
    if (v < r0) { r1 = r0; r0 = v; } else if (v < r1) { r1 = v; }
}

// ================= kernel 0: zero scratch ============
__global__ void k_zero() {
    int i = blockIdx.x * blockDim.x + threadIdx.x;
    ((float4*)g_dw)[i] = make_float4(0.f, 0.f, 0.f, 0.f);
    if (i < KC) g_counts[i] = 0.f;
}

// ================= kernel 1: norms + e4m3 quantization ==============
// One warp per row; lane holds 16 CONTIGUOUS floats (4 consecutive float4s).
__global__ void k_norms(const float* __restrict__ X, const float* __restrict__ C) {
    int warp = (blockIdx.x * blockDim.x + threadIdx.x) >> 5;
    int lane = threadIdx.x & 31;
    if (warp < KC) {
        const float4* r = (const float4*)(C + (size_t)warp * DIM);
        float s = 0.f;
        float4 v[4];
        #pragma unroll
        for (int t = 0; t < 4; t++) {
            v[t] = r[lane * 4 + t];
            s += v[t].x * v[t].x + v[t].y * v[t].y + v[t].z * v[t].z + v[t].w * v[t].w;
        }
        #pragma unroll
        for (int o = 16; o; o >>= 1) s += __shfl_xor_sync(0xFFFFFFFFu, s, o);
        if (lane == 0) g_cnorm2[warp] = s;
        uint4 pk;
        pk.x = pack4_e4m3(v[0].x * QSCALE, v[0].y * QSCALE, v[0].z * QSCALE, v[0].w * QSCALE);
        pk.y = pack4_e4m3(v[1].x * QSCALE, v[1].y * QSCALE, v[1].z * QSCALE, v[1].w * QSCALE);
        pk.z = pack4_e4m3(v[2].x * QSCALE, v[2].y * QSCALE, v[2].z * QSCALE, v[2].w * QSCALE);
        pk.w = pack4_e4m3(v[3].x * QSCALE, v[3].y * QSCALE, v[3].z * QSCALE, v[3].w * QSCALE);
        ((uint4*)(g_cq + (size_t)warp * DIM))[lane] = pk;
    } else if (warp < KC + N_PTS) {
        int row = warp - KC;
        const float4* r = (const float4*)(X + (size_t)row * DIM);
        float s = 0.f;
        float4 v[4];
        #pragma unroll
        for (int t = 0; t < 4; t++) {
            v[t] = r[lane * 4 + t];
            s += v[t].x * v[t].x + v[t].y * v[t].y + v[t].z * v[t].z + v[t].w * v[t].w;
        }
        #pragma unroll
        for (int o = 16; o; o >>= 1) s += __shfl_xor_sync(0xFFFFFFFFu, s, o);
        float in = 1.0f / fmaxf(sqrtf(s), 1e-12f);
        if (lane == 0) g_invn[row] = in;
        float sc = in * QSCALE;
        uint4 pk;
        pk.x = pack4_e4m3(v[0].x * sc, v[0].y * sc, v[0].z * sc, v[0].w * sc);
        pk.y = pack4_e4m3(v[1].x * sc, v[1].y * sc, v[1].z * sc, v[1].w * sc);
        pk.z = pack4_e4m3(v[2].x * sc, v[2].y * sc, v[2].z * sc, v[2].w * sc);
        pk.w = pack4_e4m3(v[3].x * sc, v[3].y * sc, v[3].z * sc, v[3].w * sc);
        ((uint4*)(g_xq + (size_t)row * DIM))[lane] = pk;
    }
}

// ================= kernel 2: fp8 m16n8k32 GEMM (ldmatrix + 4-stage cp.async) ============
// 512 threads = 16 warps in 4x4 grid; warp tile 32x32; block tile 128 rows x 128 cols.
__global__ __launch_bounds__(512, 1) void k_assign_mma(const float* __restrict__ X,
                                                       const float* __restrict__ C,
                                                       float* __restrict__ out) {
    extern __shared__ char dsm[];
    float* s_cn = (float*)(dsm + CNOFF);
    unsigned long long* red = (unsigned long long*)(dsm + REDOFF);
    const uint32_t sbase = (uint32_t)__cvta_generic_to_shared(dsm);

    const int tid = threadIdx.x;
    const int lane = tid & 31;
    const int wid = tid >> 5;
    const int wm = wid >> 2;
    const int wn = wid & 3;
    const int g = lane >> 2;
    const int tq = lane & 3;
    const int r0 = blockIdx.x * 128;

    // ---- A preload: 4 chunks of [128r x 128B], commit-group 0 ----
    {
        const char* xb = (const char*)g_xq + (size_t)r0 * DIM;
        #pragma unroll
        for (int t = 0; t < 8; t++) {
            int idx = tid + t * 512;              // 4096 16B segments
            int chunk = idx >> 10;
            int r = (idx >> 3) & 127;
            int s = idx & 7;
            const char* gp = xb + (size_t)r * DIM + chunk * 128 + s * 16;
            uint32_t sp = sbase + AOFF + chunk * ACH + r * 128 + ((s ^ (r & 7)) * 16);
            CP16(sp, gp);
        }
        CP_COMMIT();
    }
    for (int i = tid; i < KC; i += 512) s_cn[i] = g_cnorm2[i];

    // ---- B prologue: chunks 0,1,2 -> groups 1,2,3 (chunk ci covers ct=ci>>2, kb=ci&3) ----
    #pragma unroll
    for (int pc = 0; pc < 3; pc++) {
        const char* cb = (const char*)g_cq;
        #pragma unroll
        for (int t = 0; t < 2; t++) {
            int idx = tid + t * 512;              // 1024 segments
            int r = idx >> 3;
            int s = idx & 7;
            const char* gp = cb + (size_t)r * DIM + pc * 128 + s * 16;
            uint32_t sp = sbase + BOFF + pc * ACH + r * 128 + ((s ^ (r & 7)) * 16);
            CP16(sp, gp);
        }
        CP_COMMIT();
    }

    unsigned long long rb0 = ~0ull, rb1 = ~0ull;
    float acc[2][4][4];

    for (int ct = 0; ct < 16; ++ct) {
        #pragma unroll
        for (int mt = 0; mt < 2; mt++)
            #pragma unroll
            for (int nt = 0; nt < 4; nt++)
                #pragma unroll
                for (int c = 0; c < 4; c++) acc[mt][nt][c] = 0.f;

        for (int kb = 0; kb < 4; ++kb) {
            const int ci = ct * 4 + kb;           // 64 chunks total
            // chunk ci = commit-group ci+1; committed: 0..ci+3; wait 2 -> 0..ci+1 done.
            CP_WAIT(2);
            __syncthreads();   // publish chunk ci; stage (ci+3)&3 free to overwrite

            if (ci + 3 < 64) {
                int ct2 = (ci + 3) >> 2, kb2 = (ci + 3) & 3;
                const char* cb = (const char*)g_cq + (size_t)ct2 * 128 * DIM;
                int st = (ci + 3) & 3;
                #pragma unroll
                for (int t = 0; t < 2; t++) {
                    int idx = tid + t * 512;
                    int r = idx >> 3;
                    int s = idx & 7;
                    const char* gp = cb + (size_t)r * DIM + kb2 * 128 + s * 16;
                    uint32_t sp = sbase + BOFF + st * ACH + r * 128 + ((s ^ (r & 7)) * 16);
                    CP16(sp, gp);
                }
            }
            CP_COMMIT();

            const uint32_t Ab = sbase + AOFF + kb * ACH;
            const uint32_t Bb = sbase + BOFF + (ci & 3) * ACH;
            #pragma unroll
            for (int ks = 0; ks < 4; ks++) {      // each ks = 32B = K-step of 32 fp8
                uint32_t a[2][4];
                #pragma unroll
                for (int mt = 0; mt < 2; mt++) {
                    int r = wm * 32 + mt * 16 + (lane & 15);
                    int s = ks * 2 + (lane >> 4);
                    uint32_t ad = Ab + r * 128 + ((s ^ (r & 7)) * 16);
                    LDSM_X4(a[mt][0], a[mt][1], a[mt][2], a[mt][3], ad);
                }
                uint32_t b[4][2];
                #pragma unroll
                for (int ntp = 0; ntp < 2; ntp++) {
                    int r = wn * 32 + ntp * 16 + (lane & 15);
                    int s = ks * 2 + (lane >> 4);
                    uint32_t ad = Bb + r * 128 + ((s ^ (r & 7)) * 16);
                    uint32_t q0, q1, q2, q3;
                    LDSM_X4(q0, q1, q2, q3, ad);
                    b[ntp * 2 + 0][0] = q0; b[ntp * 2 + 0][1] = q2;
                    b[ntp * 2 + 1][0] = q1; b[ntp * 2 + 1][1] = q3;
                }
                #pragma unroll
                for (int mt = 0; mt < 2; mt++)
                    #pragma unroll
                    for (int nt = 0; nt < 4; nt++) {
                        asm volatile(
                            "mma.sync.aligned.m16n8k32.row.col.f32.e4m3.e4m3.f32 "
                            "{%0,%1,%2,%3}, {%4,%5,%6,%7}, {%8,%9}, {%0,%1,%2,%3};"
                            : "+f"(acc[mt][nt][0]), "+f"(acc[mt][nt][1]),
                              "+f"(acc[mt][nt][2]), "+f"(acc[mt][nt][3])
                            : "r"(a[mt][0]), "r"(a[mt][1]), "r"(a[mt][2]), "r"(a[mt][3]),
                              "r"(b[nt][0]), "r"(b[nt][1]));
                    }
            }
        }

        // ---- epilogue: d = cn - 2*acc/256 ; per-quad top-2 over warp's 32 cols ----
        #pragma unroll
        for (int mt = 0; mt < 2; mt++) {
            #pragma unroll
            for (int rs = 0; rs < 2; rs++) {
                unsigned long long t0 = ~0ull, t1 = ~0ull;
                #pragma unroll
                for (int nt = 0; nt < 4; nt++) {
                    #pragma unroll
                    for (int cc = 0; cc < 2; cc++) {
                        int col = ct * 128 + wn * 32 + nt * 8 + 2 * tq + cc;
                        float d = fmaf(-0.0078125f, acc[mt][nt][rs * 2 + cc], s_cn[col]);
                        ins2(packkey(d, col), t0, t1);
                    }
                }
                #pragma unroll
                for (int off = 1; off <= 2; off <<= 1) {
                    unsigned long long o0 = __shfl_xor_sync(0xFFFFFFFFu, t0, off);
                    unsigned long long o1 = __shfl_xor_sync(0xFFFFFFFFu, t1, off);
                    unsigned long long n0 = t0 < o0 ? t0 : o0;
                    unsigned long long hi = t0 < o0 ? o0 : t0;
                    unsigned long long lo1 = t1 < o1 ? t1 : o1;
                    t0 = n0;
                    t1 = hi < lo1 ? hi : lo1;
                }
                if (tq == mt * 2 + rs) { ins2(t0, rb0, rb1); ins2(t1, rb0, rb1); }
            }
        }
    }

    {
        int row = wm * 32 + (tq >> 1) * 16 + g + 8 * (tq & 1);
        red[row * 8 + wn * 2 + 0] = rb0;
        red[row * 8 + wn * 2 + 1] = rb1;
    }
    __syncthreads();

    // ---- final merge + margin filter + exact fp32 refine ----
    if (tid < 128) {
        int row = r0 + tid;
        unsigned long long kbest = ~0ull;
        #pragma unroll
        for (int i = 0; i < 8; i++) {
            unsigned long long v = red[tid * 8 + i];
            if (v < kbest) kbest = v;
        }
        float thr = unpackd(kbest) + MARGIN;
        int cols2[8], nc = 0;
        #pragma unroll
        for (int i = 0; i < 8; i++) {
            unsigned long long v = red[tid * 8 + i];
            if (unpackd(v) <= thr) cols2[nc++] = (int)(unsigned int)(v & 0xffffffffull);
        }

        int best;
        if (nc <= 1) {
            best = (int)(unsigned int)(kbest & 0xffffffffull);
        } else {
            float m2inv = -2.0f * g_invn[row];
            const float4* xr = (const float4*)(X + (size_t)row * DIM);
            unsigned long long bkey = ~0ull;
            for (int c = 0; c < nc; c++) {
                int col = cols2[c];
                const float4* cr = (const float4*)(C + (size_t)col * DIM);
                float s = 0.f;
                #pragma unroll 8
                for (int i = 0; i < 128; i++) {
                    float4 a = xr[i], b = cr[i];
                    s = fmaf(a.x, b.x, s); s = fmaf(a.y, b.y, s);
                    s = fmaf(a.z, b.z, s); s = fmaf(a.w, b.w, s);
                }
                float d = fmaf(m2inv, s, s_cn[col]);
                unsigned long long key = packkey(d, col);
                if (key < bkey) bkey = key;
            }
            best = (int)(unsigned int)(bkey & 0xffffffffull);
        }
        g_idx[row] = best;
        out[OFF_IDX + row] = (float)best;
        atomicAdd(&g_counts[best], 1.0f);
    }
}

// ================= kernel 3: quantized gather + dw scatter ========
__global__ void k_scatter(const float* __restrict__ X, const float* __restrict__ C,
                          float* __restrict__ out) {
    int row  = blockIdx.x * 8 + (threadIdx.x >> 5);
    int lane = threadIdx.x & 31;
    int k = g_idx[row];
    const float4* c4 = (const float4*)(C + (size_t)k * DIM);
    const float4* x4 = (const float4*)(X + (size_t)row * DIM);
    float4* q4 = (float4*)(out + OFF_Q + (size_t)row * DIM);
    float* dwr = g_dw + (size_t)k * DIM;
    #pragma unroll
    for (int i = lane; i < DIM / 4; i += 32) {
        q4[i] = c4[i];
        float4 v = x4[i];
        atomicAdd(dwr + i * 4 + 0, v.x);
        atomicAdd(dwr + i * 4 + 1, v.y);
        atomicAdd(dwr + i * 4 + 2, v.z);
        atomicAdd(dwr + i * 4 + 3, v.w);
    }
}

// ================= kernel 4: EMA cluster size =====================
__global__ void k_size(const float* __restrict__ ema_size, float* __restrict__ out) {
    __shared__ float s0[KC];
    __shared__ float part[1024];
    int tid = threadIdx.x;
    const float om = 1.0f - DECAYF;
    float local = 0.f;
    for (int k = tid; k < KC; k += 1024) {
        float v = ema_size[k] * DECAYF + om * g_counts[k];
        s0[k] = v;
        local += v;
    }
    part[tid] = local;
    __syncthreads();
    for (int o = 512; o > 0; o >>= 1) {
        if (tid < o) part[tid] += part[tid + o];
        __syncthreads();
    }
    float n = part[0];
    float denom = n + (float)KC * 1e-5f;
    for (int k = tid; k < KC; k += 1024) {
        float ns = (s0[k] + 1e-5f) / denom * n;
        out[OFF_NS + k] = ns;
        g_ns[k] = ns;
    }
}

// ================= kernel 5: new_w + new_centroids ================
__global__ void k_final(const float* __restrict__ ema_w, float* __restrict__ out) {
    int i = blockIdx.x * blockDim.x + threadIdx.x;
    int k = i >> 7;
    const float om = 1.0f - DECAYF;
    float4 w = ((const float4*)ema_w)[i];
    float4 d = ((const float4*)g_dw)[i];
    float4 nw;
    nw.x = w.x * DECAYF + om * d.x;
    nw.y = w.y * DECAYF + om * d.y;
    nw.z = w.z * DECAYF + om * d.z;
    nw.w = w.w * DECAYF + om * d.w;
    ((float4*)(out + OFF_NW))[i] = nw;
    float ns = __ldg(&g_ns[k]);
    float4 nc;
    nc.x = nw.x / ns;
    nc.y = nw.y / ns;
    nc.z = nw.z / ns;
    nc.w = nw.w / ns;
    ((float4*)(out + OFF_NC))[i] = nc;
}

// ================= launch ========================================
extern "C" void kernel_launch(void* const* d_in, const int* in_sizes, int n_in,
                              void* d_out, int out_size) {
    const float* X        = (const float*)d_in[0];
    const float* C        = (const float*)d_in[1];
    const float* ema_size = (const float*)d_in[2];
    const float* ema_w    = (const float*)d_in[3];
    float* out = (float*)d_out;

    cudaFuncSetAttribute(k_assign_mma, cudaFuncAttributeMaxDynamicSharedMemorySize, SMEM_DYN);

    k_zero      <<<(KC * DIM / 4) / 256, 256>>>();
    k_norms     <<<(KC + N_PTS) / 8, 256>>>(X, C);
    k_assign_mma<<<N_PTS / 128, 512, SMEM_DYN>>>(X, C, out);
    k_scatter   <<<N_PTS / 8, 256>>>(X, C, out);
    k_size      <<<1, 1024>>>(ema_size, out);
    k_final     <<<(KC * DIM / 4) / 256, 256>>>(ema_w, out);
}